// round 9
// baseline (speedup 1.0000x reference)
#include <cuda_runtime.h>
#include <cuda_fp16.h>
#include <math.h>
#include <stdint.h>

#define B_ 16
#define S_ 2048
#define D_ 256
#define C2 4.8828125e-6f   // 0.01 * 2/(B*D)

// ---- scratch ----
__device__ __align__(16) float  g_s2[S_ * B_ * D_];   // [t][b][j] fp32
__device__ __align__(16) __half g_r2h[S_ * B_ * D_];  // [t][b][j] fp16
__device__ __align__(16) float  g_v2[B_ * S_ * D_];

// ============================================================================
// Kernel 1: precompute  s = tanh(a1*x), r = half(s + noise), v = tanh(a2*x)
// ============================================================================
__global__ void precompute_kernel(const float* __restrict__ x,
                                  const float* __restrict__ noise,
                                  const float* __restrict__ a1,
                                  const float* __restrict__ a2) {
    int bid = blockIdx.x;
    int t = bid & (S_ - 1);
    int b = bid >> 11;
    int j = threadIdx.x;
    size_t gi = ((size_t)(b * S_ + t)) * D_ + j;
    float xv = x[gi];
    float nv = noise[gi];
    float sv = tanhf(a1[j] * xv);
    size_t si = ((size_t)(t * B_ + b)) * D_ + j;
    g_s2[si] = sv;
    g_r2h[si] = __float2half(sv + nv);
    g_v2[gi] = tanhf(a2[j] * xv);
}

// ============================================================================
// PTX helpers
// ============================================================================
__device__ __forceinline__ uint32_t smem_u32(const void* p) {
    return (uint32_t)__cvta_generic_to_shared(p);
}
__device__ __forceinline__ void mbar_init(uint32_t mb, uint32_t count) {
    asm volatile("mbarrier.init.shared.b64 [%0], %1;" :: "r"(mb), "r"(count) : "memory");
}
__device__ __forceinline__ void mbar_expect_tx(uint32_t mb, uint32_t bytes) {
    asm volatile("mbarrier.arrive.expect_tx.shared.b64 _, [%0], %1;"
                 :: "r"(mb), "r"(bytes) : "memory");
}
__device__ __forceinline__ void mbar_wait(uint32_t mb, uint32_t parity) {
    asm volatile(
        "{\n\t"
        ".reg .pred P;\n\t"
        "LAB_W_%=:\n\t"
        "mbarrier.try_wait.parity.acquire.cta.shared::cta.b64 P, [%0], %1, 0x989680;\n\t"
        "@P bra LAB_D_%=;\n\t"
        "bra LAB_W_%=;\n\t"
        "LAB_D_%=:\n\t"
        "}"
        :: "r"(mb), "r"(parity) : "memory");
}
__device__ __forceinline__ void bulk_g2s(uint32_t dst, const void* src, uint32_t bytes,
                                         uint32_t mb) {
    asm volatile(
        "cp.async.bulk.shared::cta.global.mbarrier::complete_tx::bytes [%0], [%1], %2, [%3];"
        :: "r"(dst), "l"(src), "r"(bytes), "r"(mb) : "memory");
}

__device__ __forceinline__ float dot8(float4 a0, float4 a1, float4 b0, float4 b1) {
    float acc = a0.x * b0.x;
    acc = fmaf(a0.y, b0.y, acc);
    acc = fmaf(a0.z, b0.z, acc);
    acc = fmaf(a0.w, b0.w, acc);
    acc = fmaf(a1.x, b1.x, acc);
    acc = fmaf(a1.y, b1.y, acc);
    acc = fmaf(a1.z, b1.z, acc);
    acc = fmaf(a1.w, b1.w, acc);
    return acc;
}

__device__ __forceinline__ float merge2(float a, float b, int lane, int delta) {
    bool hi = (lane & delta) != 0;
    float t = hi ? a : b;
    float o = __shfl_xor_sync(0xffffffffu, t, delta);
    return (hi ? b : a) + o;
}

__device__ __forceinline__ float4 h4_to_f4(uint2 u) {
    float2 f0 = __half22float2(*(__half2*)&u.x);
    float2 f1 = __half22float2(*(__half2*)&u.y);
    return make_float4(f0.x, f0.y, f1.x, f1.y);
}

// ============================================================================
// Kernel 2: TTT scan. 128 CTAs x 256 threads (8 warps); CTA owns 2 rows of W.
// 4-deep TMA ring: r (fp16, 8KB/step) + s (fp32, 16KB/step), one mbar each buf.
// Per step: C (W update from diff,r_t) -> bar -> BD (out_t = W s_t;
//   diff_{t+1} = W r_{t+1} - s_{t+1}, subtracted at store) -> bar.
// smem: [0,32768) r ring (4x8KB) | [32768,98304) s ring (4x16KB)
//       | shW [2][256] | shd float2[16] | mbar[4]
// ============================================================================
#define NBUF 4
#define RBUF_BYTES 8192
#define SBUF_BYTES 16384
#define SM_S 32768
#define SM_W 98304
#define SM_D 100352
#define SM_MBAR 100480
#define SMEM_BYTES 100608

__global__ void __launch_bounds__(256, 1) scan_kernel(const float* __restrict__ W0,
                                                      float* __restrict__ out) {
    extern __shared__ __align__(16) char smem[];
    float* shW = (float*)(smem + SM_W);
    float* shd = (float*)(smem + SM_D);

    const int tid = threadIdx.x;
    const int lane = tid & 31;
    const int lane4 = lane * 4;
    const int row0 = blockIdx.x * 2;
    const int b0 = (tid >> 5) * 2;
    const int b1 = b0 + 1;

    const uint32_t mbar_base = smem_u32(smem + SM_MBAR);
    const uint32_t sm_base = smem_u32(smem);

    float w0 = W0[(size_t)row0 * D_ + tid];
    float w1 = W0[(size_t)(row0 + 1) * D_ + tid];
    shW[tid] = w0;
    shW[256 + tid] = w1;

    if (tid == 0) {
#pragma unroll
        for (int k = 0; k < NBUF; k++) mbar_init(mbar_base + 8 * k, 1);
        asm volatile("fence.proxy.async.shared::cta;" ::: "memory");
    }
    __syncthreads();

    // prologue: fill all 4 buffers (steps 0..3)
    if (tid == 0) {
#pragma unroll
        for (int k = 0; k < NBUF; k++) {
            uint32_t mb = mbar_base + 8 * k;
            mbar_expect_tx(mb, RBUF_BYTES + SBUF_BYTES);
            bulk_g2s(sm_base + k * RBUF_BYTES, (const char*)g_r2h + (size_t)k * RBUF_BYTES,
                     RBUF_BYTES, mb);
            bulk_g2s(sm_base + SM_S + k * SBUF_BYTES,
                     (const char*)g_s2 + (size_t)k * SBUF_BYTES, SBUF_BYTES, mb);
        }
    }

    // prologue: diff_0 = W_0 r_0 - s_0[rows]
    mbar_wait(mbar_base, 0);
    {
        const __half* rb_h = (const __half*)smem;
        const float* sb = (const float*)(smem + SM_S);
        float4 r00 = h4_to_f4(*(const uint2*)&rb_h[b0 * 256 + lane4]);
        float4 r01 = h4_to_f4(*(const uint2*)&rb_h[b0 * 256 + 128 + lane4]);
        float4 r10 = h4_to_f4(*(const uint2*)&rb_h[b1 * 256 + lane4]);
        float4 r11 = h4_to_f4(*(const uint2*)&rb_h[b1 * 256 + 128 + lane4]);
        float4 wa0 = *(const float4*)&shW[lane4];
        float4 wa1 = *(const float4*)&shW[128 + lane4];
        float4 wb0 = *(const float4*)&shW[256 + lane4];
        float4 wb1 = *(const float4*)&shW[256 + 128 + lane4];
        float d00 = dot8(r00, r01, wa0, wa1);
        float d01 = dot8(r00, r01, wb0, wb1);
        float d10 = dot8(r10, r11, wa0, wa1);
        float d11 = dot8(r10, r11, wb0, wb1);
        float m0 = merge2(d00, d01, lane, 16);  // bit4 -> row
        float m1 = merge2(d10, d11, lane, 16);
        float q = merge2(m0, m1, lane, 8);      // bit3 -> batch
        q += __shfl_xor_sync(0xffffffffu, q, 4);
        q += __shfl_xor_sync(0xffffffffu, q, 2);
        q += __shfl_xor_sync(0xffffffffu, q, 1);
        float v1 = __shfl_xor_sync(0xffffffffu, q, 16);  // row1 partner
        if ((lane & 23) == 0) {  // lanes 0, 8
            int bsel = (lane & 8) ? b1 : b0;
            float2 sv = *(const float2*)&sb[bsel * 256 + row0];
            *(float2*)&shd[bsel * 2] = make_float2(q - sv.x, v1 - sv.y);
        }
    }

#pragma unroll 1
    for (int t = 0; t < S_; t++) {
        const int buf = t & (NBUF - 1);
        const __half* rb_h = (const __half*)(smem + buf * RBUF_BYTES);
        const float* sb = (const float*)(smem + SM_S + buf * SBUF_BYTES);
        const bool haveNext = (t + 1 < S_);

        __syncthreads();  // shd valid; buffer (t-1) fully consumed; BD done with shW

        if (tid == 0 && t >= 1 && t + 3 < S_) {
            const int nb = (t + 3) & (NBUF - 1);
            const uint32_t mb = mbar_base + 8 * nb;
            mbar_expect_tx(mb, RBUF_BYTES + SBUF_BYTES);
            bulk_g2s(sm_base + nb * RBUF_BYTES,
                     (const char*)g_r2h + (size_t)(t + 3) * RBUF_BYTES, RBUF_BYTES, mb);
            bulk_g2s(sm_base + SM_S + nb * SBUF_BYTES,
                     (const char*)g_s2 + (size_t)(t + 3) * SBUF_BYTES, SBUF_BYTES, mb);
        }

        // ---- Phase C: W[i,j] -= C2 * sum_b diff[b,i] * r_t[b,j];  j = tid ----
        {
            const float4* df = (const float4*)shd;
            float acc0 = 0.0f, acc1 = 0.0f;
#pragma unroll
            for (int k = 0; k < 8; k++) {
                float4 f = df[k];  // {b=2k: row0,row1 ; b=2k+1: row0,row1}
                float ra = __half2float(rb_h[(2 * k) * 256 + tid]);
                float rc = __half2float(rb_h[(2 * k + 1) * 256 + tid]);
                acc0 = fmaf(f.x, ra, acc0);
                acc1 = fmaf(f.y, ra, acc1);
                acc0 = fmaf(f.z, rc, acc0);
                acc1 = fmaf(f.w, rc, acc1);
            }
            w0 = fmaf(-C2, acc0, w0);
            w1 = fmaf(-C2, acc1, w1);
            shW[tid] = w0;
            shW[256 + tid] = w1;
        }
        __syncthreads();

        // ---- Phase BD: out_t = W s_t ; diff_{t+1} = W r_{t+1} - s_{t+1} ----
        {
            float4 wa0 = *(const float4*)&shW[lane4];
            float4 wa1 = *(const float4*)&shW[128 + lane4];
            float4 wb0 = *(const float4*)&shW[256 + lane4];
            float4 wb1 = *(const float4*)&shW[256 + 128 + lane4];

            float4 s00 = *(const float4*)&sb[b0 * 256 + lane4];
            float4 s01 = *(const float4*)&sb[b0 * 256 + 128 + lane4];
            float4 s10 = *(const float4*)&sb[b1 * 256 + lane4];
            float4 s11 = *(const float4*)&sb[b1 * 256 + 128 + lane4];

            float o00 = dot8(s00, s01, wa0, wa1);
            float o01 = dot8(s00, s01, wb0, wb1);
            float o10 = dot8(s10, s11, wa0, wa1);
            float o11 = dot8(s10, s11, wb0, wb1);

            float d00 = 0.f, d01 = 0.f, d10 = 0.f, d11 = 0.f;
            const float* sn = sb;
            if (haveNext) {
                const int nb = (t + 1) & (NBUF - 1);
                mbar_wait(mbar_base + 8 * nb, ((t + 1) >> 2) & 1);
                const __half* rn = (const __half*)(smem + nb * RBUF_BYTES);
                sn = (const float*)(smem + SM_S + nb * SBUF_BYTES);
                float4 r00 = h4_to_f4(*(const uint2*)&rn[b0 * 256 + lane4]);
                float4 r01 = h4_to_f4(*(const uint2*)&rn[b0 * 256 + 128 + lane4]);
                float4 r10 = h4_to_f4(*(const uint2*)&rn[b1 * 256 + lane4]);
                float4 r11 = h4_to_f4(*(const uint2*)&rn[b1 * 256 + 128 + lane4]);
                d00 = dot8(r00, r01, wa0, wa1);
                d01 = dot8(r00, r01, wb0, wb1);
                d10 = dot8(r10, r11, wa0, wa1);
                d11 = dot8(r10, r11, wb0, wb1);
            }

            // 9-shfl merged reduce: bit4 -> row, bit3 -> batch, bit2 -> out/d
            float m0 = merge2(o00, o01, lane, 16);
            float m1 = merge2(o10, o11, lane, 16);
            float m2 = merge2(d00, d01, lane, 16);
            float m3 = merge2(d10, d11, lane, 16);
            float q0 = merge2(m0, m1, lane, 8);
            float q1 = merge2(m2, m3, lane, 8);
            float u = merge2(q0, q1, lane, 4);
            u += __shfl_xor_sync(0xffffffffu, u, 2);
            u += __shfl_xor_sync(0xffffffffu, u, 1);
            float v1 = __shfl_xor_sync(0xffffffffu, u, 16);  // row1 partner

            if ((lane & 19) == 0) {  // lanes 0, 4, 8, 12
                int bsel = (lane & 8) ? b1 : b0;
                if (lane & 4) {
                    if (haveNext) {
                        float2 sv = *(const float2*)&sn[bsel * 256 + row0];
                        *(float2*)&shd[bsel * 2] = make_float2(u - sv.x, v1 - sv.y);
                    }
                } else {
                    __stcs((float2*)&out[((size_t)bsel * S_ + t) * D_ + row0],
                           make_float2(u, v1));
                }
            }
        }
    }
}

// ============================================================================
// Kernel 3: FF path GEMM + fused epilogue, accumulates into out.
// ============================================================================
#define GM 128
#define GN 64
#define GK 32

__device__ __forceinline__ float ffu(float v, float a, float b, float gam, float eta) {
    float z = a * v;
    float gel = 0.5f * z * (1.0f + erff(z * 0.70710678118654752f));
    return gam * gel + eta * sinf(b * v);
}

__global__ void __launch_bounds__(256) ff_kernel(const float* __restrict__ Wp,
                                                 const float* __restrict__ ffa,
                                                 const float* __restrict__ ffb,
                                                 const float* __restrict__ ffg,
                                                 const float* __restrict__ ffe,
                                                 float* __restrict__ out) {
    __shared__ float As[GK][GM + 4];
    __shared__ float Bs[GK][GN + 4];

    const int tid = threadIdx.x;
    const int m0 = blockIdx.x * GM;
    const int n0 = blockIdx.y * GN;
    const int tm = (tid >> 4) * 8;
    const int tn = (tid & 15) * 4;
    const int ar = tid >> 3;
    const int ac = (tid & 7) * 4;

    float acc[8][4];
#pragma unroll
    for (int i = 0; i < 8; i++)
#pragma unroll
        for (int jj = 0; jj < 4; jj++) acc[i][jj] = 0.0f;

    for (int k0 = 0; k0 < D_; k0 += GK) {
#pragma unroll
        for (int p = 0; p < 4; p++) {
            float4 av = *(const float4*)&g_v2[(size_t)(m0 + ar + 32 * p) * D_ + k0 + ac];
            As[ac + 0][ar + 32 * p] = av.x;
            As[ac + 1][ar + 32 * p] = av.y;
            As[ac + 2][ar + 32 * p] = av.z;
            As[ac + 3][ar + 32 * p] = av.w;
        }
#pragma unroll
        for (int p = 0; p < 2; p++) {
            float4 bv = *(const float4*)&Wp[(size_t)(n0 + ar + 32 * p) * D_ + k0 + ac];
            Bs[ac + 0][ar + 32 * p] = bv.x;
            Bs[ac + 1][ar + 32 * p] = bv.y;
            Bs[ac + 2][ar + 32 * p] = bv.z;
            Bs[ac + 3][ar + 32 * p] = bv.w;
        }
        __syncthreads();
#pragma unroll
        for (int kk = 0; kk < GK; kk++) {
            float4 a0 = *(const float4*)&As[kk][tm];
            float4 a1 = *(const float4*)&As[kk][tm + 4];
            float4 b0 = *(const float4*)&Bs[kk][tn];
            float am[8] = {a0.x, a0.y, a0.z, a0.w, a1.x, a1.y, a1.z, a1.w};
            float bn[4] = {b0.x, b0.y, b0.z, b0.w};
#pragma unroll
            for (int i = 0; i < 8; i++)
#pragma unroll
                for (int jj = 0; jj < 4; jj++)
                    acc[i][jj] = fmaf(am[i], bn[jj], acc[i][jj]);
        }
        __syncthreads();
    }

    const float gam = ffg[0];
    const float eta = ffe[0];
    const float4 fa = *(const float4*)&ffa[n0 + tn];
    const float4 fb = *(const float4*)&ffb[n0 + tn];
#pragma unroll
    for (int i = 0; i < 8; i++) {
        size_t base = (size_t)(m0 + tm + i) * D_ + n0 + tn;
        float4 vv = *(const float4*)&g_v2[base];
        float4 ov = *(const float4*)&out[base];
        float4 res;
        res.x = ov.x + ffu(vv.x, fa.x, fb.x, gam, eta) * acc[i][0];
        res.y = ov.y + ffu(vv.y, fa.y, fb.y, gam, eta) * acc[i][1];
        res.z = ov.z + ffu(vv.z, fa.z, fb.z, gam, eta) * acc[i][2];
        res.w = ov.w + ffu(vv.w, fa.w, fb.w, gam, eta) * acc[i][3];
        *(float4*)&out[base] = res;
    }
}

// ============================================================================
extern "C" void kernel_launch(void* const* d_in, const int* in_sizes, int n_in,
                              void* d_out, int out_size) {
    const float* x     = (const float*)d_in[0];
    const float* noise = (const float*)d_in[1];
    const float* a1    = (const float*)d_in[2];
    const float* a2    = (const float*)d_in[3];
    const float* Wttt  = (const float*)d_in[4];
    const float* Wproj = (const float*)d_in[5];
    const float* ffa   = (const float*)d_in[6];
    const float* ffb   = (const float*)d_in[7];
    const float* ffg   = (const float*)d_in[8];
    const float* ffe   = (const float*)d_in[9];
    float* out = (float*)d_out;

    cudaFuncSetAttribute(scan_kernel, cudaFuncAttributeMaxDynamicSharedMemorySize,
                         SMEM_BYTES);

    precompute_kernel<<<B_ * S_, 256>>>(x, noise, a1, a2);
    scan_kernel<<<128, 256, SMEM_BYTES>>>(Wttt, out);
    ff_kernel<<<dim3(B_ * S_ / GM, D_ / GN), 256>>>(Wproj, ffa, ffb, ffg, ffe, out);
}

// round 12
// speedup vs baseline: 1.7714x; 1.7714x over previous
#include <cuda_runtime.h>
#include <math.h>
#include <stdint.h>

#define B_ 16
#define S_ 2048
#define D_ 256
#define C2 4.8828125e-6f   // 0.01 * 2/(B*D)

// ---- scratch ----
__device__ __align__(16) float g_s2[S_ * B_ * D_];  // [t][b][j]
__device__ __align__(16) float g_r2[S_ * B_ * D_];  // [t][b][j]
__device__ __align__(16) float g_v2[B_ * S_ * D_];

// ============================================================================
// Kernel 1: precompute  s = tanh(a1*x), r = s + noise, v = tanh(a2*x)
// ============================================================================
__global__ void precompute_kernel(const float* __restrict__ x,
                                  const float* __restrict__ noise,
                                  const float* __restrict__ a1,
                                  const float* __restrict__ a2) {
    int bid = blockIdx.x;
    int t = bid & (S_ - 1);
    int b = bid >> 11;
    int j = threadIdx.x;
    size_t gi = ((size_t)(b * S_ + t)) * D_ + j;
    float xv = x[gi];
    float nv = noise[gi];
    float sv = tanhf(a1[j] * xv);
    size_t si = ((size_t)(t * B_ + b)) * D_ + j;
    g_s2[si] = sv;
    g_r2[si] = sv + nv;
    g_v2[gi] = tanhf(a2[j] * xv);
}

// ============================================================================
// PTX helpers
// ============================================================================
__device__ __forceinline__ uint32_t smem_u32(const void* p) {
    return (uint32_t)__cvta_generic_to_shared(p);
}
__device__ __forceinline__ void mbar_init(uint32_t mb, uint32_t count) {
    asm volatile("mbarrier.init.shared.b64 [%0], %1;" :: "r"(mb), "r"(count) : "memory");
}
__device__ __forceinline__ void mbar_expect_tx(uint32_t mb, uint32_t bytes) {
    asm volatile("mbarrier.arrive.expect_tx.shared.b64 _, [%0], %1;"
                 :: "r"(mb), "r"(bytes) : "memory");
}
__device__ __forceinline__ void mbar_wait(uint32_t mb, uint32_t parity) {
    asm volatile(
        "{\n\t"
        ".reg .pred P;\n\t"
        "LAB_W_%=:\n\t"
        "mbarrier.try_wait.parity.acquire.cta.shared::cta.b64 P, [%0], %1, 0x989680;\n\t"
        "@P bra LAB_D_%=;\n\t"
        "bra LAB_W_%=;\n\t"
        "LAB_D_%=:\n\t"
        "}"
        :: "r"(mb), "r"(parity) : "memory");
}
__device__ __forceinline__ void bulk_g2s(uint32_t dst, const void* src, uint32_t bytes,
                                         uint32_t mb) {
    asm volatile(
        "cp.async.bulk.shared::cta.global.mbarrier::complete_tx::bytes [%0], [%1], %2, [%3];"
        :: "r"(dst), "l"(src), "r"(bytes), "r"(mb) : "memory");
}

__device__ __forceinline__ float dot8(float4 a0, float4 a1, float4 b0, float4 b1) {
    float acc = a0.x * b0.x;
    acc = fmaf(a0.y, b0.y, acc);
    acc = fmaf(a0.z, b0.z, acc);
    acc = fmaf(a0.w, b0.w, acc);
    acc = fmaf(a1.x, b1.x, acc);
    acc = fmaf(a1.y, b1.y, acc);
    acc = fmaf(a1.z, b1.z, acc);
    acc = fmaf(a1.w, b1.w, acc);
    return acc;
}

// Merge two per-warp partial sums across xor-distance `delta`.
__device__ __forceinline__ float merge2(float a, float b, int lane, int delta) {
    bool hi = (lane & delta) != 0;
    float t = hi ? a : b;
    float o = __shfl_xor_sync(0xffffffffu, t, delta);
    return (hi ? b : a) + o;
}

// ============================================================================
// Kernel 2: TTT scan. 128 CTAs x 256 threads; CTA owns 2 rows of W.
// Per step: C (W update from diff_t, r_t) -> barrier -> BD (out_t = W s_t,
// diff_{t+1} = W r_{t+1} - s_{t+1} subtracted at store) -> barrier.
// 4-deep TMA ring for (r,s) step blocks (fp32, 32KB/buffer: r 16KB + s 16KB).
// shd holds diff (s already subtracted), layout float2[b] = {row0,row1}.
// ============================================================================
#define NBUF 4
#define BUF_BYTES 32768
#define SM_W 131072
#define SM_D 133120
#define SM_MBAR 133248
#define SMEM_BYTES 133376

__global__ void __launch_bounds__(256, 1) scan_kernel(const float* __restrict__ W0,
                                                      float* __restrict__ out) {
    extern __shared__ __align__(16) char smem[];
    float* shW = (float*)(smem + SM_W);
    float* shd = (float*)(smem + SM_D);

    const int tid = threadIdx.x;
    const int warp = tid >> 5;
    const int lane = tid & 31;
    const int lane4 = lane * 4;
    const int row0 = blockIdx.x * 2;
    const int b0 = warp * 2;
    const int b1 = b0 + 1;

    const uint32_t mbar_base = smem_u32(smem + SM_MBAR);
    const uint32_t sm_base = smem_u32(smem);

    float w0 = W0[(size_t)row0 * D_ + tid];
    float w1 = W0[(size_t)(row0 + 1) * D_ + tid];
    shW[tid] = w0;
    shW[256 + tid] = w1;

    if (tid == 0) {
#pragma unroll
        for (int k = 0; k < NBUF; k++) mbar_init(mbar_base + 8 * k, 1);
        asm volatile("fence.proxy.async.shared::cta;" ::: "memory");
    }
    __syncthreads();

    // prologue: fill all 4 buffers (steps 0..3)
    if (tid == 0) {
#pragma unroll
        for (int k = 0; k < NBUF; k++) {
            uint32_t mb = mbar_base + 8 * k;
            mbar_expect_tx(mb, BUF_BYTES);
            bulk_g2s(sm_base + k * BUF_BYTES, (const char*)g_r2 + (size_t)k * 16384,
                     16384, mb);
            bulk_g2s(sm_base + k * BUF_BYTES + 16384, (const char*)g_s2 + (size_t)k * 16384,
                     16384, mb);
        }
    }

    // prologue: diff_0 = W_0 r_0 - s_0[rows]
    mbar_wait(mbar_base, 0);
    {
        const float* rb = (const float*)(smem);  // buf 0 r
        const float* sb = rb + 4096;             // buf 0 s
        float4 r00 = *(const float4*)&rb[b0 * 256 + lane4];
        float4 r01 = *(const float4*)&rb[b0 * 256 + 128 + lane4];
        float4 r10 = *(const float4*)&rb[b1 * 256 + lane4];
        float4 r11 = *(const float4*)&rb[b1 * 256 + 128 + lane4];
        float4 wa0 = *(const float4*)&shW[lane4];
        float4 wa1 = *(const float4*)&shW[128 + lane4];
        float4 wb0 = *(const float4*)&shW[256 + lane4];
        float4 wb1 = *(const float4*)&shW[256 + 128 + lane4];
        float d00 = dot8(r00, r01, wa0, wa1);
        float d01 = dot8(r00, r01, wb0, wb1);
        float d10 = dot8(r10, r11, wa0, wa1);
        float d11 = dot8(r10, r11, wb0, wb1);
        float m0 = merge2(d00, d01, lane, 16);  // bit4 -> row
        float m1 = merge2(d10, d11, lane, 16);
        float q = merge2(m0, m1, lane, 8);      // bit3 -> batch
        q += __shfl_xor_sync(0xffffffffu, q, 4);
        q += __shfl_xor_sync(0xffffffffu, q, 2);
        q += __shfl_xor_sync(0xffffffffu, q, 1);
        float v1 = __shfl_xor_sync(0xffffffffu, q, 16);  // row1 partner
        if ((lane & 23) == 0) {  // lanes 0, 8 (bit4==0): hold row0=q, row1=v1
            int bsel = (lane & 8) ? b1 : b0;
            float2 sv = *(const float2*)&sb[bsel * 256 + row0];
            *(float2*)&shd[bsel * 2] = make_float2(q - sv.x, v1 - sv.y);
        }
    }

#pragma unroll 1
    for (int t = 0; t < S_; t++) {
        const int buf = t & (NBUF - 1);
        const float* rb = (const float*)(smem + buf * BUF_BYTES);

        __syncthreads();  // shd valid; buffer (t-1) free

        if (tid == 0 && t >= 1 && t + 3 < S_) {
            const int nb = (t + 3) & (NBUF - 1);
            const uint32_t mb = mbar_base + 8 * nb;
            mbar_expect_tx(mb, BUF_BYTES);
            bulk_g2s(sm_base + nb * BUF_BYTES, (const char*)g_r2 + (size_t)(t + 3) * 16384,
                     16384, mb);
            bulk_g2s(sm_base + nb * BUF_BYTES + 16384,
                     (const char*)g_s2 + (size_t)(t + 3) * 16384, 16384, mb);
        }

        // ---- Phase C: W[i,j] -= C2 * sum_b diff[b,i] * r_t[b,j];  j = tid ----
        {
            float acc0 = 0.0f, acc1 = 0.0f;
            const float4* df4 = (const float4*)shd;
#pragma unroll
            for (int k = 0; k < 8; k++) {
                float4 f = df4[k];  // {b=2k: row0,row1 ; b=2k+1: row0,row1}
                float ra = rb[(2 * k) * 256 + tid];
                float rc = rb[(2 * k + 1) * 256 + tid];
                acc0 = fmaf(f.x, ra, acc0);
                acc1 = fmaf(f.y, ra, acc1);
                acc0 = fmaf(f.z, rc, acc0);
                acc1 = fmaf(f.w, rc, acc1);
            }
            w0 = fmaf(-C2, acc0, w0);
            w1 = fmaf(-C2, acc1, w1);
            shW[tid] = w0;
            shW[256 + tid] = w1;
        }
        __syncthreads();

        // ---- Phase BD: out_t = W s_t ; diff_{t+1} = W r_{t+1} - s_{t+1} ----
        {
            const float* sb = rb + 4096;
            float4 s00 = *(const float4*)&sb[b0 * 256 + lane4];
            float4 s01 = *(const float4*)&sb[b0 * 256 + 128 + lane4];
            float4 s10 = *(const float4*)&sb[b1 * 256 + lane4];
            float4 s11 = *(const float4*)&sb[b1 * 256 + 128 + lane4];
            float4 wa0 = *(const float4*)&shW[lane4];
            float4 wa1 = *(const float4*)&shW[128 + lane4];
            float4 wb0 = *(const float4*)&shW[256 + lane4];
            float4 wb1 = *(const float4*)&shW[256 + 128 + lane4];
            float o00 = dot8(s00, s01, wa0, wa1);
            float o01 = dot8(s00, s01, wb0, wb1);
            float o10 = dot8(s10, s11, wa0, wa1);
            float o11 = dot8(s10, s11, wb0, wb1);

            float d00 = 0.f, d01 = 0.f, d10 = 0.f, d11 = 0.f;
            const float* sn = sb;
            if (t + 1 < S_) {
                const int nb = (t + 1) & (NBUF - 1);
                mbar_wait(mbar_base + 8 * nb, ((t + 1) >> 2) & 1);
                const float* rn = (const float*)(smem + nb * BUF_BYTES);
                sn = rn + 4096;
                float4 r00 = *(const float4*)&rn[b0 * 256 + lane4];
                float4 r01 = *(const float4*)&rn[b0 * 256 + 128 + lane4];
                float4 r10 = *(const float4*)&rn[b1 * 256 + lane4];
                float4 r11 = *(const float4*)&rn[b1 * 256 + 128 + lane4];
                d00 = dot8(r00, r01, wa0, wa1);
                d01 = dot8(r00, r01, wb0, wb1);
                d10 = dot8(r10, r11, wa0, wa1);
                d11 = dot8(r10, r11, wb0, wb1);
            }

            // 9-shfl merged reduce: bit4 -> row, bit3 -> batch, bit2 -> out/d
            float m0 = merge2(o00, o01, lane, 16);
            float m1 = merge2(o10, o11, lane, 16);
            float m2 = merge2(d00, d01, lane, 16);
            float m3 = merge2(d10, d11, lane, 16);
            float q0 = merge2(m0, m1, lane, 8);
            float q1 = merge2(m2, m3, lane, 8);
            float u = merge2(q0, q1, lane, 4);
            u += __shfl_xor_sync(0xffffffffu, u, 2);
            u += __shfl_xor_sync(0xffffffffu, u, 1);
            float v1 = __shfl_xor_sync(0xffffffffu, u, 16);  // row1 partner

            if ((lane & 19) == 0) {  // lanes 0, 4, 8, 12 (bit4==0): row0=u, row1=v1
                int bsel = (lane & 8) ? b1 : b0;
                if (lane & 4) {
                    if (t + 1 < S_) {
                        float2 sv = *(const float2*)&sn[bsel * 256 + row0];
                        *(float2*)&shd[bsel * 2] = make_float2(u - sv.x, v1 - sv.y);
                    }
                } else {
                    *(float2*)&out[((size_t)bsel * S_ + t) * D_ + row0] = make_float2(u, v1);
                }
            }
        }
    }
}

// ============================================================================
// Kernel 3: FF path GEMM + fused epilogue, accumulates into out.
// ============================================================================
#define GM 128
#define GN 64
#define GK 32

__device__ __forceinline__ float ffu(float v, float a, float b, float gam, float eta) {
    float z = a * v;
    float gel = 0.5f * z * (1.0f + erff(z * 0.70710678118654752f));
    return gam * gel + eta * sinf(b * v);
}

__global__ void __launch_bounds__(256) ff_kernel(const float* __restrict__ Wp,
                                                 const float* __restrict__ ffa,
                                                 const float* __restrict__ ffb,
                                                 const float* __restrict__ ffg,
                                                 const float* __restrict__ ffe,
                                                 float* __restrict__ out) {
    __shared__ float As[GK][GM + 4];
    __shared__ float Bs[GK][GN + 4];

    const int tid = threadIdx.x;
    const int m0 = blockIdx.x * GM;
    const int n0 = blockIdx.y * GN;
    const int tm = (tid >> 4) * 8;
    const int tn = (tid & 15) * 4;
    const int ar = tid >> 3;
    const int ac = (tid & 7) * 4;

    float acc[8][4];
#pragma unroll
    for (int i = 0; i < 8; i++)
#pragma unroll
        for (int jj = 0; jj < 4; jj++) acc[i][jj] = 0.0f;

    for (int k0 = 0; k0 < D_; k0 += GK) {
#pragma unroll
        for (int p = 0; p < 4; p++) {
            float4 av = *(const float4*)&g_v2[(size_t)(m0 + ar + 32 * p) * D_ + k0 + ac];
            As[ac + 0][ar + 32 * p] = av.x;
            As[ac + 1][ar + 32 * p] = av.y;
            As[ac + 2][ar + 32 * p] = av.z;
            As[ac + 3][ar + 32 * p] = av.w;
        }
#pragma unroll
        for (int p = 0; p < 2; p++) {
            float4 bv = *(const float4*)&Wp[(size_t)(n0 + ar + 32 * p) * D_ + k0 + ac];
            Bs[ac + 0][ar + 32 * p] = bv.x;
            Bs[ac + 1][ar + 32 * p] = bv.y;
            Bs[ac + 2][ar + 32 * p] = bv.z;
            Bs[ac + 3][ar + 32 * p] = bv.w;
        }
        __syncthreads();
#pragma unroll
        for (int kk = 0; kk < GK; kk++) {
            float4 a0 = *(const float4*)&As[kk][tm];
            float4 a1 = *(const float4*)&As[kk][tm + 4];
            float4 b0 = *(const float4*)&Bs[kk][tn];
            float am[8] = {a0.x, a0.y, a0.z, a0.w, a1.x, a1.y, a1.z, a1.w};
            float bn[4] = {b0.x, b0.y, b0.z, b0.w};
#pragma unroll
            for (int i = 0; i < 8; i++)
#pragma unroll
                for (int jj = 0; jj < 4; jj++)
                    acc[i][jj] = fmaf(am[i], bn[jj], acc[i][jj]);
        }
        __syncthreads();
    }

    const float gam = ffg[0];
    const float eta = ffe[0];
    const float4 fa = *(const float4*)&ffa[n0 + tn];
    const float4 fb = *(const float4*)&ffb[n0 + tn];
#pragma unroll
    for (int i = 0; i < 8; i++) {
        size_t base = (size_t)(m0 + tm + i) * D_ + n0 + tn;
        float4 vv = *(const float4*)&g_v2[base];
        float4 ov = *(const float4*)&out[base];
        float4 res;
        res.x = ov.x + ffu(vv.x, fa.x, fb.x, gam, eta) * acc[i][0];
        res.y = ov.y + ffu(vv.y, fa.y, fb.y, gam, eta) * acc[i][1];
        res.z = ov.z + ffu(vv.z, fa.z, fb.z, gam, eta) * acc[i][2];
        res.w = ov.w + ffu(vv.w, fa.w, fb.w, gam, eta) * acc[i][3];
        *(float4*)&out[base] = res;
    }
}

// ============================================================================
extern "C" void kernel_launch(void* const* d_in, const int* in_sizes, int n_in,
                              void* d_out, int out_size) {
    const float* x     = (const float*)d_in[0];
    const float* noise = (const float*)d_in[1];
    const float* a1    = (const float*)d_in[2];
    const float* a2    = (const float*)d_in[3];
    const float* Wttt  = (const float*)d_in[4];
    const float* Wproj = (const float*)d_in[5];
    const float* ffa   = (const float*)d_in[6];
    const float* ffb   = (const float*)d_in[7];
    const float* ffg   = (const float*)d_in[8];
    const float* ffe   = (const float*)d_in[9];
    float* out = (float*)d_out;

    cudaFuncSetAttribute(scan_kernel, cudaFuncAttributeMaxDynamicSharedMemorySize,
                         SMEM_BYTES);

    precompute_kernel<<<B_ * S_, 256>>>(x, noise, a1, a2);
    scan_kernel<<<128, 256, SMEM_BYTES>>>(Wttt, out);
    ff_kernel<<<dim3(B_ * S_ / GM, D_ / GN), 256>>>(Wproj, ffa, ffb, ffg, ffe, out);
}